// round 12
// baseline (speedup 1.0000x reference)
#include <cuda_runtime.h>
#include <cuda_bf16.h>
#include <cstdint>
#include <cstddef>

#define DI __device__ __forceinline__

static constexpr int N_ROWS = 8192;   // batch rows
static constexpr int D_IN   = 2048;
static constexpr int D_H    = 8192;
static constexpr int D_OUT  = 2048;

// ---------------- scratch (device globals; no allocation allowed) ----------
__device__ __align__(16) __nv_bfloat16 g_w1q[(size_t)D_H  * D_IN ];  // 32 MB
__device__ __align__(16) __nv_bfloat16 g_w2q[(size_t)D_OUT * D_H ];  // 32 MB
__device__ __align__(16) __nv_bfloat16 g_xhi[(size_t)N_ROWS * D_IN]; // 32 MB
__device__ __align__(16) __nv_bfloat16 g_xlo[(size_t)N_ROWS * D_IN]; // 32 MB
__device__ __align__(16) float         g_h  [(size_t)N_ROWS * D_H ]; // 256 MB
__device__ __align__(16) __nv_bfloat16 g_hhi[(size_t)N_ROWS * D_H ]; // 128 MB
__device__ __align__(16) __nv_bfloat16 g_hlo[(size_t)N_ROWS * D_H ]; // 128 MB
__device__ __align__(16) float         g_o  [(size_t)N_ROWS * D_OUT];// 64 MB

// ---------------- PTX helpers ----------------------------------------------
DI uint32_t smem_u32(const void* p){ return (uint32_t)__cvta_generic_to_shared(p); }

DI void cp_async16(uint32_t dst, const void* src){
    asm volatile("cp.async.cg.shared.global [%0], [%1], 16;\n" :: "r"(dst), "l"(src));
}
DI void cp_commit(){ asm volatile("cp.async.commit_group;\n"); }
template<int N> DI void cp_wait(){ asm volatile("cp.async.wait_group %0;\n" :: "n"(N)); }

DI void ldsm4(uint32_t& r0, uint32_t& r1, uint32_t& r2, uint32_t& r3, uint32_t a){
    asm volatile("ldmatrix.sync.aligned.m8n8.x4.shared.b16 {%0,%1,%2,%3}, [%4];\n"
        : "=r"(r0), "=r"(r1), "=r"(r2), "=r"(r3) : "r"(a));
}
DI void mma16816(float* d, const uint32_t* a, uint32_t b0, uint32_t b1){
    asm volatile("mma.sync.aligned.m16n8k16.row.col.f32.bf16.bf16.f32 "
        "{%0,%1,%2,%3}, {%4,%5,%6,%7}, {%8,%9}, {%0,%1,%2,%3};\n"
        : "+f"(d[0]), "+f"(d[1]), "+f"(d[2]), "+f"(d[3])
        : "r"(a[0]), "r"(a[1]), "r"(a[2]), "r"(a[3]), "r"(b0), "r"(b1));
}

// ---------------- GEMM: C = (Ahi+Alo) @ B^T, epilogue (acc+bias)*scale ------
static constexpr int BM = 128, BN = 128, BK = 64, STAGES = 3;
static constexpr int TILE_BYTES  = BM * BK * 2;            // 16384 (one bf16 tile)
static constexpr int STAGE_BYTES = TILE_BYTES * 3;         // a_hi + a_lo + b
static constexpr int GEMM_SMEM   = STAGE_BYTES * STAGES;   // 147456

// 128 rows x 64 bf16 (128B rows). 16B-chunk swizzle: phys_chunk = chunk ^ (row&7).
DI void load_tile64(char* dst, const __nv_bfloat16* __restrict__ src,
                    int ld, int row0, int k0, int tid){
    #pragma unroll
    for (int i = 0; i < 4; i++){
        int lin = tid + i * 256;
        int r = lin >> 3;
        int c = lin & 7;
        int cs = c ^ (r & 7);
        cp_async16(smem_u32(dst + ((r << 6) + (cs << 3)) * 2),
                   src + (size_t)(row0 + r) * ld + k0 + (c << 3));
    }
}

template<int LAYER, int Mdim, int Ndim, int Kdim>
__global__ __launch_bounds__(256, 1)
void gemm_kernel(const float* __restrict__ bias, const float* __restrict__ scale){
    extern __shared__ char smem[];
    const __nv_bfloat16* Ahi = (LAYER == 1) ? g_xhi : g_hhi;
    const __nv_bfloat16* Alo = (LAYER == 1) ? g_xlo : g_hlo;
    const __nv_bfloat16* Bw  = (LAYER == 1) ? g_w1q : g_w2q;
    float* C = (LAYER == 1) ? g_h : g_o;

    constexpr int NBN = Ndim / BN;
    constexpr int KT  = Kdim / BK;

    // CTA swizzle: groups of 8 M-blocks share B columns in L2
    int bid = blockIdx.x;
    int grp = bid / (8 * NBN);
    int rem = bid % (8 * NBN);
    int bm  = grp * 8 + (rem & 7);
    int bn  = rem >> 3;

    int tid  = threadIdx.x;
    int lane = tid & 31;
    int wid  = tid >> 5;
    int wm   = (wid >> 2) * 64;   // 0 / 64
    int wn   = (wid & 3) * 32;    // 0 / 32 / 64 / 96

    // prologue: stages 0 .. STAGES-2
    #pragma unroll
    for (int s = 0; s < STAGES - 1; ++s){
        char* st = smem + s * STAGE_BYTES;
        load_tile64(st,                  Ahi, Kdim, bm * BM, s * BK, tid);
        load_tile64(st + TILE_BYTES,     Alo, Kdim, bm * BM, s * BK, tid);
        load_tile64(st + 2 * TILE_BYTES, Bw,  Kdim, bn * BN, s * BK, tid);
        cp_commit();
    }

    float acc[4][4][4];
    #pragma unroll
    for (int i = 0; i < 4; i++)
        #pragma unroll
        for (int j = 0; j < 4; j++)
            #pragma unroll
            for (int k = 0; k < 4; k++) acc[i][j][k] = 0.f;

    int cidx = 0, pidx = STAGES - 1;
    for (int kt = 0; kt < KT; ++kt){
        cp_wait<STAGES - 2>();
        __syncthreads();

        if (kt + STAGES - 1 < KT){
            char* st = smem + pidx * STAGE_BYTES;
            int k0 = (kt + STAGES - 1) * BK;
            load_tile64(st,                  Ahi, Kdim, bm * BM, k0, tid);
            load_tile64(st + TILE_BYTES,     Alo, Kdim, bm * BM, k0, tid);
            load_tile64(st + 2 * TILE_BYTES, Bw,  Kdim, bn * BN, k0, tid);
        }
        cp_commit();

        char* st = smem + cidx * STAGE_BYTES;
        uint32_t sa = smem_u32(st);
        uint32_t sl = sa + TILE_BYTES;
        uint32_t sb = sa + 2 * TILE_BYTES;

        #pragma unroll
        for (int kk = 0; kk < 4; ++kk){
            uint32_t ah[4][4], al[4][4], bb[2][4];
            #pragma unroll
            for (int mi = 0; mi < 4; mi++){
                int r  = wm + mi * 16 + (lane & 15);
                int ch = ((kk << 1) + (lane >> 4)) ^ (r & 7);
                uint32_t off = (uint32_t)((r << 6) + (ch << 3)) * 2;
                ldsm4(ah[mi][0], ah[mi][1], ah[mi][2], ah[mi][3], sa + off);
                ldsm4(al[mi][0], al[mi][1], al[mi][2], al[mi][3], sl + off);
            }
            #pragma unroll
            for (int pj = 0; pj < 2; pj++){
                int r  = wn + pj * 16 + (lane & 15);
                int ch = ((kk << 1) + (lane >> 4)) ^ (r & 7);
                uint32_t off = (uint32_t)((r << 6) + (ch << 3)) * 2;
                ldsm4(bb[pj][0], bb[pj][1], bb[pj][2], bb[pj][3], sb + off);
            }
            #pragma unroll
            for (int mi = 0; mi < 4; mi++)
                #pragma unroll
                for (int ni = 0; ni < 4; ni++)
                    mma16816(acc[mi][ni], ah[mi], bb[ni >> 1][ni & 1], bb[ni >> 1][(ni & 1) + 2]);
            #pragma unroll
            for (int mi = 0; mi < 4; mi++)
                #pragma unroll
                for (int ni = 0; ni < 4; ni++)
                    mma16816(acc[mi][ni], al[mi], bb[ni >> 1][ni & 1], bb[ni >> 1][(ni & 1) + 2]);
        }
        if (++cidx == STAGES) cidx = 0;
        if (++pidx == STAGES) pidx = 0;
    }

    // epilogue: (acc + bias[n]) * scale[n], fp32 out
    float2 bsv[4], ssv[4];
    #pragma unroll
    for (int ni = 0; ni < 4; ni++){
        int c = bn * BN + wn + ni * 8 + ((lane & 3) << 1);
        bsv[ni] = *(const float2*)&bias[c];
        ssv[ni] = *(const float2*)&scale[c];
    }
    #pragma unroll
    for (int mi = 0; mi < 4; mi++){
        #pragma unroll
        for (int hh = 0; hh < 2; ++hh){
            int r = bm * BM + wm + mi * 16 + hh * 8 + (lane >> 2);
            #pragma unroll
            for (int ni = 0; ni < 4; ni++){
                int c = bn * BN + wn + ni * 8 + ((lane & 3) << 1);
                float2 o;
                o.x = (acc[mi][ni][hh * 2 + 0] + bsv[ni].x) * ssv[ni].x;
                o.y = (acc[mi][ni][hh * 2 + 1] + bsv[ni].y) * ssv[ni].y;
                *(float2*)&C[(size_t)r * Ndim + c] = o;
            }
        }
    }
}

// ---------------- reductions / LayerNorm ------------------------------------
DI float block_reduce(float v, volatile float* buf){
    #pragma unroll
    for (int o = 16; o; o >>= 1) v += __shfl_xor_sync(0xffffffffu, v, o);
    int w = threadIdx.x >> 5, l = threadIdx.x & 31;
    if (l == 0) buf[w] = v;
    __syncthreads();
    if (threadIdx.x < 32){
        v = (l < 8) ? buf[l] : 0.f;
        #pragma unroll
        for (int o = 4; o; o >>= 1) v += __shfl_xor_sync(0xffffffffu, v, o);
        if (l == 0) buf[0] = v;
    }
    __syncthreads();
    return buf[0];
}

// LN(+relu) over D_H, then split to bf16 hi/lo for GEMM2
__global__ __launch_bounds__(256)
void ln1_kernel(const float* __restrict__ gam, const float* __restrict__ bet){
    __shared__ float red[40];
    size_t row = blockIdx.x;
    const float4* h4 = (const float4*)(g_h + row * D_H);
    float4 v[8];
    float sum = 0.f, sq = 0.f;
    #pragma unroll
    for (int i = 0; i < 8; i++){
        v[i] = h4[threadIdx.x + i * 256];
        sum += v[i].x + v[i].y + v[i].z + v[i].w;
        sq  += v[i].x * v[i].x + v[i].y * v[i].y + v[i].z * v[i].z + v[i].w * v[i].w;
    }
    sum = block_reduce(sum, red);
    sq  = block_reduce(sq,  red + 20);
    float mu   = sum * (1.f / D_H);
    float var  = sq * (1.f / D_H) - mu * mu;
    float rstd = rsqrtf(var + 1e-5f);

    __nv_bfloat16* hhi = g_hhi + row * D_H;
    __nv_bfloat16* hlo = g_hlo + row * D_H;
    #pragma unroll
    for (int i = 0; i < 8; i++){
        int c = (threadIdx.x + i * 256) * 4;
        float4 gg = *(const float4*)&gam[c];
        float4 bb = *(const float4*)&bet[c];
        float y0 = fmaxf((v[i].x - mu) * rstd * gg.x + bb.x, 0.f);
        float y1 = fmaxf((v[i].y - mu) * rstd * gg.y + bb.y, 0.f);
        float y2 = fmaxf((v[i].z - mu) * rstd * gg.z + bb.z, 0.f);
        float y3 = fmaxf((v[i].w - mu) * rstd * gg.w + bb.w, 0.f);
        __nv_bfloat16 h0 = __float2bfloat16(y0), h1 = __float2bfloat16(y1);
        __nv_bfloat16 h2 = __float2bfloat16(y2), h3 = __float2bfloat16(y3);
        __nv_bfloat162 p;
        p.x = h0; p.y = h1; *(__nv_bfloat162*)&hhi[c]     = p;
        p.x = h2; p.y = h3; *(__nv_bfloat162*)&hhi[c + 2] = p;
        p.x = __float2bfloat16(y0 - __bfloat162float(h0));
        p.y = __float2bfloat16(y1 - __bfloat162float(h1));
        *(__nv_bfloat162*)&hlo[c] = p;
        p.x = __float2bfloat16(y2 - __bfloat162float(h2));
        p.y = __float2bfloat16(y3 - __bfloat162float(h3));
        *(__nv_bfloat162*)&hlo[c + 2] = p;
    }
}

// final LN over D_OUT -> d_out (fp32)
__global__ __launch_bounds__(256)
void ln2_kernel(const float* __restrict__ gam, const float* __restrict__ bet,
                float* __restrict__ out){
    __shared__ float red[40];
    size_t row = blockIdx.x;
    const float4* o4 = (const float4*)(g_o + row * D_OUT);
    float4 v[2];
    float sum = 0.f, sq = 0.f;
    #pragma unroll
    for (int i = 0; i < 2; i++){
        v[i] = o4[threadIdx.x + i * 256];
        sum += v[i].x + v[i].y + v[i].z + v[i].w;
        sq  += v[i].x * v[i].x + v[i].y * v[i].y + v[i].z * v[i].z + v[i].w * v[i].w;
    }
    sum = block_reduce(sum, red);
    sq  = block_reduce(sq,  red + 20);
    float mu   = sum * (1.f / D_OUT);
    float var  = sq * (1.f / D_OUT) - mu * mu;
    float rstd = rsqrtf(var + 1e-5f);

    float4* out4 = (float4*)(out + row * D_OUT);
    #pragma unroll
    for (int i = 0; i < 2; i++){
        int idx = threadIdx.x + i * 256;
        int c = idx * 4;
        float4 gg = *(const float4*)&gam[c];
        float4 bb = *(const float4*)&bet[c];
        float4 r;
        r.x = (v[i].x - mu) * rstd * gg.x + bb.x;
        r.y = (v[i].y - mu) * rstd * gg.y + bb.y;
        r.z = (v[i].z - mu) * rstd * gg.z + bb.z;
        r.w = (v[i].w - mu) * rstd * gg.w + bb.w;
        out4[idx] = r;
    }
}

// ---------------- prep: ternary-quantize weights, split activations ---------
DI float ternf(float x){ return (fabsf(x) < 0.1f) ? 0.f : (x > 0.f ? 1.f : -1.f); }

__global__ __launch_bounds__(256)
void quant_kernel(const float* __restrict__ w, int which){
    __nv_bfloat16* q = (which == 1) ? g_w1q : g_w2q;
    size_t i = (size_t)blockIdx.x * 256 + threadIdx.x;
    float4 v = ((const float4*)w)[i];
    __nv_bfloat162 p;
    p.x = __float2bfloat16(ternf(v.x)); p.y = __float2bfloat16(ternf(v.y));
    *(__nv_bfloat162*)&q[i * 4] = p;
    p.x = __float2bfloat16(ternf(v.z)); p.y = __float2bfloat16(ternf(v.w));
    *(__nv_bfloat162*)&q[i * 4 + 2] = p;
}

__global__ __launch_bounds__(256)
void splitx_kernel(const float* __restrict__ x){
    size_t i = (size_t)blockIdx.x * 256 + threadIdx.x;
    float4 v = ((const float4*)x)[i];
    __nv_bfloat16 h0 = __float2bfloat16(v.x), h1 = __float2bfloat16(v.y);
    __nv_bfloat16 h2 = __float2bfloat16(v.z), h3 = __float2bfloat16(v.w);
    __nv_bfloat162 p;
    p.x = h0; p.y = h1; *(__nv_bfloat162*)&g_xhi[i * 4]     = p;
    p.x = h2; p.y = h3; *(__nv_bfloat162*)&g_xhi[i * 4 + 2] = p;
    p.x = __float2bfloat16(v.x - __bfloat162float(h0));
    p.y = __float2bfloat16(v.y - __bfloat162float(h1));
    *(__nv_bfloat162*)&g_xlo[i * 4] = p;
    p.x = __float2bfloat16(v.z - __bfloat162float(h2));
    p.y = __float2bfloat16(v.w - __bfloat162float(h3));
    *(__nv_bfloat162*)&g_xlo[i * 4 + 2] = p;
}

// ---------------- launch -----------------------------------------------------
extern "C" void kernel_launch(void* const* d_in, const int* in_sizes, int n_in,
                              void* d_out, int out_size){
    const float* x    = (const float*)d_in[0];
    const float* w1   = (const float*)d_in[1];
    const float* b1   = (const float*)d_in[2];
    const float* s1   = (const float*)d_in[3];
    const float* w2   = (const float*)d_in[4];
    const float* b2   = (const float*)d_in[5];
    const float* s2   = (const float*)d_in[6];
    const float* ln1g = (const float*)d_in[7];
    const float* ln1b = (const float*)d_in[8];
    const float* outg = (const float*)d_in[9];
    const float* outb = (const float*)d_in[10];
    float* out = (float*)d_out;

    // >48KB dynamic smem opt-in (persistent per-function; harmless if it
    // no-ops during capture since the correctness call already set it)
    (void)cudaFuncSetAttribute(gemm_kernel<1, N_ROWS, D_H, D_IN>,
                               cudaFuncAttributeMaxDynamicSharedMemorySize, GEMM_SMEM);
    (void)cudaFuncSetAttribute(gemm_kernel<2, N_ROWS, D_OUT, D_H>,
                               cudaFuncAttributeMaxDynamicSharedMemorySize, GEMM_SMEM);

    // 16,777,216 elems each / 4 (float4) / 256 threads = 16384 blocks
    quant_kernel<<<16384, 256>>>(w1, 1);
    quant_kernel<<<16384, 256>>>(w2, 2);
    splitx_kernel<<<16384, 256>>>(x);

    gemm_kernel<1, N_ROWS, D_H, D_IN>
        <<<(N_ROWS / BM) * (D_H / BN), 256, GEMM_SMEM>>>(b1, s1);
    ln1_kernel<<<N_ROWS, 256>>>(ln1g, ln1b);
    gemm_kernel<2, N_ROWS, D_OUT, D_H>
        <<<(N_ROWS / BM) * (D_OUT / BN), 256, GEMM_SMEM>>>(b2, s2);
    ln2_kernel<<<N_ROWS, 256>>>(outg, outb, out);
}

// round 15
// speedup vs baseline: 1.0215x; 1.0215x over previous
#include <cuda_runtime.h>
#include <cuda_bf16.h>
#include <cstdint>
#include <cstddef>

#define DI __device__ __forceinline__

static constexpr int N_ROWS = 8192;   // batch rows
static constexpr int D_IN   = 2048;
static constexpr int D_H    = 8192;
static constexpr int D_OUT  = 2048;

// ---------------- scratch (device globals; no allocation allowed) ----------
__device__ __align__(16) __nv_bfloat16 g_w1q[(size_t)D_H  * D_IN ];
__device__ __align__(16) __nv_bfloat16 g_w2q[(size_t)D_OUT * D_H ];
__device__ __align__(16) __nv_bfloat16 g_xhi[(size_t)N_ROWS * D_IN];
__device__ __align__(16) __nv_bfloat16 g_xlo[(size_t)N_ROWS * D_IN];
__device__ __align__(16) float         g_h  [(size_t)N_ROWS * D_H ];
__device__ __align__(16) __nv_bfloat16 g_hhi[(size_t)N_ROWS * D_H ];
__device__ __align__(16) __nv_bfloat16 g_hlo[(size_t)N_ROWS * D_H ];
__device__ __align__(16) float         g_o  [(size_t)N_ROWS * D_OUT];

// ---------------- PTX helpers ----------------------------------------------
DI uint32_t smem_u32(const void* p){ return (uint32_t)__cvta_generic_to_shared(p); }

DI void cp_async16(uint32_t dst, const void* src){
    asm volatile("cp.async.cg.shared.global [%0], [%1], 16;\n" :: "r"(dst), "l"(src));
}
DI void cp_commit(){ asm volatile("cp.async.commit_group;\n"); }
template<int N> DI void cp_wait(){ asm volatile("cp.async.wait_group %0;\n" :: "n"(N)); }

DI void ldsm4(uint32_t& r0, uint32_t& r1, uint32_t& r2, uint32_t& r3, uint32_t a){
    asm volatile("ldmatrix.sync.aligned.m8n8.x4.shared.b16 {%0,%1,%2,%3}, [%4];\n"
        : "=r"(r0), "=r"(r1), "=r"(r2), "=r"(r3) : "r"(a));
}
DI void mma16816(float* d, const uint32_t* a, uint32_t b0, uint32_t b1){
    asm volatile("mma.sync.aligned.m16n8k16.row.col.f32.bf16.bf16.f32 "
        "{%0,%1,%2,%3}, {%4,%5,%6,%7}, {%8,%9}, {%0,%1,%2,%3};\n"
        : "+f"(d[0]), "+f"(d[1]), "+f"(d[2]), "+f"(d[3])
        : "r"(a[0]), "r"(a[1]), "r"(a[2]), "r"(a[3]), "r"(b0), "r"(b1));
}

// ---------------- GEMM: C = (Ahi+Alo) @ B^T, epilogue (acc+bias)*scale ------
// CTA tile 128x256x64, 8 warps in 2x4 -> warp tile 64x64.
static constexpr int BM = 128, BN = 256, BK = 64, STAGES = 3;
static constexpr int A_BYTES     = BM * BK * 2;             // 16384
static constexpr int B_BYTES     = BN * BK * 2;             // 32768
static constexpr int STAGE_BYTES = 2 * A_BYTES + B_BYTES;   // 65536
static constexpr int SM_BIAS     = 0;                       // 256 floats
static constexpr int SM_SCALE    = 1024;                    // 256 floats
static constexpr int SM_STAGE0   = 2048;
static constexpr int GEMM_SMEM   = SM_STAGE0 + STAGES * STAGE_BYTES;  // 198656

// tile: ROWS rows x 64 bf16 (128B rows). 16B-chunk swizzle: phys_chunk = chunk^(row&7).
template<int ROWS>
DI void load_tile(char* dst, const __nv_bfloat16* __restrict__ src,
                  int ld, int row0, int k0, int tid){
    #pragma unroll
    for (int i = 0; i < ROWS / 32; i++){
        int lin = tid + i * 256;
        int r = lin >> 3;
        int c = lin & 7;
        int cs = c ^ (r & 7);
        cp_async16(smem_u32(dst + ((r << 6) + (cs << 3)) * 2),
                   src + (size_t)(row0 + r) * ld + k0 + (c << 3));
    }
}

template<int LAYER, int Ndim, int Kdim>
__global__ __launch_bounds__(256, 1)
void gemm_kernel(const float* __restrict__ bias, const float* __restrict__ scale){
    extern __shared__ char smem[];
    const __nv_bfloat16* Ahi = (LAYER == 1) ? g_xhi : g_hhi;
    const __nv_bfloat16* Alo = (LAYER == 1) ? g_xlo : g_hlo;
    const __nv_bfloat16* Bw  = (LAYER == 1) ? g_w1q : g_w2q;
    float* C = (LAYER == 1) ? g_h : g_o;

    constexpr int NBN = Ndim / BN;
    constexpr int KT  = Kdim / BK;

    // CTA swizzle: groups of 8 M-blocks share B columns in L2
    int bid = blockIdx.x;
    int grp = bid / (8 * NBN);
    int rem = bid % (8 * NBN);
    int bm  = grp * 8 + (rem & 7);
    int bn  = rem >> 3;

    int tid  = threadIdx.x;
    int lane = tid & 31;
    int wid  = tid >> 5;
    int wm   = (wid >> 2) * 64;   // 0 / 64
    int wn   = (wid & 3) * 64;    // 0 / 64 / 128 / 192

    // stage bias/scale for this CTA's 256 output cols
    ((float*)(smem + SM_BIAS ))[tid] = bias [bn * BN + tid];
    ((float*)(smem + SM_SCALE))[tid] = scale[bn * BN + tid];

    // prologue: stages 0 .. STAGES-2
    #pragma unroll
    for (int s = 0; s < STAGES - 1; ++s){
        char* st = smem + SM_STAGE0 + s * STAGE_BYTES;
        load_tile<BM>(st,               Ahi, Kdim, bm * BM, s * BK, tid);
        load_tile<BM>(st + A_BYTES,     Alo, Kdim, bm * BM, s * BK, tid);
        load_tile<BN>(st + 2 * A_BYTES, Bw,  Kdim, bn * BN, s * BK, tid);
        cp_commit();
    }

    float acc[4][8][4];
    #pragma unroll
    for (int i = 0; i < 4; i++)
        #pragma unroll
        for (int j = 0; j < 8; j++)
            #pragma unroll
            for (int k = 0; k < 4; k++) acc[i][j][k] = 0.f;

    int cidx = 0, pidx = STAGES - 1;
    for (int kt = 0; kt < KT; ++kt){
        cp_wait<STAGES - 2>();
        __syncthreads();

        if (kt + STAGES - 1 < KT){
            char* st = smem + SM_STAGE0 + pidx * STAGE_BYTES;
            int k0 = (kt + STAGES - 1) * BK;
            load_tile<BM>(st,               Ahi, Kdim, bm * BM, k0, tid);
            load_tile<BM>(st + A_BYTES,     Alo, Kdim, bm * BM, k0, tid);
            load_tile<BN>(st + 2 * A_BYTES, Bw,  Kdim, bn * BN, k0, tid);
        }
        cp_commit();

        char* st = smem + SM_STAGE0 + cidx * STAGE_BYTES;
        uint32_t sa = smem_u32(st);
        uint32_t sl = sa + A_BYTES;
        uint32_t sb = sa + 2 * A_BYTES;

        #pragma unroll
        for (int kk = 0; kk < 4; ++kk){
            // B fragments: 64 N-rows = 4 ldsm.x4 groups
            uint32_t bb[4][4];
            #pragma unroll
            for (int pj = 0; pj < 4; pj++){
                int r  = wn + pj * 16 + (lane & 15);
                int ch = ((kk << 1) + (lane >> 4)) ^ (r & 7);
                uint32_t off = (uint32_t)((r << 6) + (ch << 3)) * 2;
                ldsm4(bb[pj][0], bb[pj][1], bb[pj][2], bb[pj][3], sb + off);
            }
            // A hi then A lo, reusing one fragment array
            #pragma unroll
            for (int p = 0; p < 2; p++){
                uint32_t base = p ? sl : sa;
                uint32_t aa[4][4];
                #pragma unroll
                for (int mi = 0; mi < 4; mi++){
                    int r  = wm + mi * 16 + (lane & 15);
                    int ch = ((kk << 1) + (lane >> 4)) ^ (r & 7);
                    uint32_t off = (uint32_t)((r << 6) + (ch << 3)) * 2;
                    ldsm4(aa[mi][0], aa[mi][1], aa[mi][2], aa[mi][3], base + off);
                }
                #pragma unroll
                for (int mi = 0; mi < 4; mi++)
                    #pragma unroll
                    for (int ni = 0; ni < 8; ni++)
                        mma16816(acc[mi][ni], aa[mi],
                                 bb[ni >> 1][ni & 1], bb[ni >> 1][(ni & 1) + 2]);
            }
        }
        if (++cidx == STAGES) cidx = 0;
        if (++pidx == STAGES) pidx = 0;
    }

    // epilogue: (acc + bias[n]) * scale[n], fp32 out
    const float* sbv = (const float*)(smem + SM_BIAS);
    const float* ssv = (const float*)(smem + SM_SCALE);
    #pragma unroll
    for (int mi = 0; mi < 4; mi++){
        #pragma unroll
        for (int hh = 0; hh < 2; ++hh){
            int r = bm * BM + wm + mi * 16 + hh * 8 + (lane >> 2);
            float* Crow = C + (size_t)r * Ndim + bn * BN;
            #pragma unroll
            for (int ni = 0; ni < 8; ni++){
                int c = wn + ni * 8 + ((lane & 3) << 1);
                float2 o;
                o.x = (acc[mi][ni][hh * 2 + 0] + sbv[c + 0]) * ssv[c + 0];
                o.y = (acc[mi][ni][hh * 2 + 1] + sbv[c + 1]) * ssv[c + 1];
                *(float2*)&Crow[c] = o;
            }
        }
    }
}

// ---------------- reductions / LayerNorm ------------------------------------
DI float block_reduce(float v, volatile float* buf){
    #pragma unroll
    for (int o = 16; o; o >>= 1) v += __shfl_xor_sync(0xffffffffu, v, o);
    int w = threadIdx.x >> 5, l = threadIdx.x & 31;
    if (l == 0) buf[w] = v;
    __syncthreads();
    if (threadIdx.x < 32){
        v = (l < 8) ? buf[l] : 0.f;
        #pragma unroll
        for (int o = 4; o; o >>= 1) v += __shfl_xor_sync(0xffffffffu, v, o);
        if (l == 0) buf[0] = v;
    }
    __syncthreads();
    return buf[0];
}

// LN(+relu) over D_H, then split to bf16 hi/lo for GEMM2
__global__ __launch_bounds__(256)
void ln1_kernel(const float* __restrict__ gam, const float* __restrict__ bet){
    __shared__ float red[40];
    size_t row = blockIdx.x;
    const float4* h4 = (const float4*)(g_h + row * D_H);
    float4 v[8];
    float sum = 0.f, sq = 0.f;
    #pragma unroll
    for (int i = 0; i < 8; i++){
        v[i] = h4[threadIdx.x + i * 256];
        sum += v[i].x + v[i].y + v[i].z + v[i].w;
        sq  += v[i].x * v[i].x + v[i].y * v[i].y + v[i].z * v[i].z + v[i].w * v[i].w;
    }
    sum = block_reduce(sum, red);
    sq  = block_reduce(sq,  red + 20);
    float mu   = sum * (1.f / D_H);
    float var  = sq * (1.f / D_H) - mu * mu;
    float rstd = rsqrtf(var + 1e-5f);

    __nv_bfloat16* hhi = g_hhi + row * D_H;
    __nv_bfloat16* hlo = g_hlo + row * D_H;
    #pragma unroll
    for (int i = 0; i < 8; i++){
        int c = (threadIdx.x + i * 256) * 4;
        float4 gg = *(const float4*)&gam[c];
        float4 bb = *(const float4*)&bet[c];
        float y0 = fmaxf((v[i].x - mu) * rstd * gg.x + bb.x, 0.f);
        float y1 = fmaxf((v[i].y - mu) * rstd * gg.y + bb.y, 0.f);
        float y2 = fmaxf((v[i].z - mu) * rstd * gg.z + bb.z, 0.f);
        float y3 = fmaxf((v[i].w - mu) * rstd * gg.w + bb.w, 0.f);
        __nv_bfloat16 h0 = __float2bfloat16(y0), h1 = __float2bfloat16(y1);
        __nv_bfloat16 h2 = __float2bfloat16(y2), h3 = __float2bfloat16(y3);
        __nv_bfloat162 p;
        p.x = h0; p.y = h1; *(__nv_bfloat162*)&hhi[c]     = p;
        p.x = h2; p.y = h3; *(__nv_bfloat162*)&hhi[c + 2] = p;
        p.x = __float2bfloat16(y0 - __bfloat162float(h0));
        p.y = __float2bfloat16(y1 - __bfloat162float(h1));
        *(__nv_bfloat162*)&hlo[c] = p;
        p.x = __float2bfloat16(y2 - __bfloat162float(h2));
        p.y = __float2bfloat16(y3 - __bfloat162float(h3));
        *(__nv_bfloat162*)&hlo[c + 2] = p;
    }
}

// final LN over D_OUT -> d_out (fp32)
__global__ __launch_bounds__(256)
void ln2_kernel(const float* __restrict__ gam, const float* __restrict__ bet,
                float* __restrict__ out){
    __shared__ float red[40];
    size_t row = blockIdx.x;
    const float4* o4 = (const float4*)(g_o + row * D_OUT);
    float4 v[2];
    float sum = 0.f, sq = 0.f;
    #pragma unroll
    for (int i = 0; i < 2; i++){
        v[i] = o4[threadIdx.x + i * 256];
        sum += v[i].x + v[i].y + v[i].z + v[i].w;
        sq  += v[i].x * v[i].x + v[i].y * v[i].y + v[i].z * v[i].z + v[i].w * v[i].w;
    }
    sum = block_reduce(sum, red);
    sq  = block_reduce(sq,  red + 20);
    float mu   = sum * (1.f / D_OUT);
    float var  = sq * (1.f / D_OUT) - mu * mu;
    float rstd = rsqrtf(var + 1e-5f);

    float4* out4 = (float4*)(out + row * D_OUT);
    #pragma unroll
    for (int i = 0; i < 2; i++){
        int idx = threadIdx.x + i * 256;
        int c = idx * 4;
        float4 gg = *(const float4*)&gam[c];
        float4 bb = *(const float4*)&bet[c];
        float4 r;
        r.x = (v[i].x - mu) * rstd * gg.x + bb.x;
        r.y = (v[i].y - mu) * rstd * gg.y + bb.y;
        r.z = (v[i].z - mu) * rstd * gg.z + bb.z;
        r.w = (v[i].w - mu) * rstd * gg.w + bb.w;
        out4[idx] = r;
    }
}

// ---------------- prep: ternary-quantize weights, split activations ---------
DI float ternf(float x){ return (fabsf(x) < 0.1f) ? 0.f : (x > 0.f ? 1.f : -1.f); }

__global__ __launch_bounds__(256)
void quant_kernel(const float* __restrict__ w, int which){
    __nv_bfloat16* q = (which == 1) ? g_w1q : g_w2q;
    size_t i = (size_t)blockIdx.x * 256 + threadIdx.x;
    float4 v = ((const float4*)w)[i];
    __nv_bfloat162 p;
    p.x = __float2bfloat16(ternf(v.x)); p.y = __float2bfloat16(ternf(v.y));
    *(__nv_bfloat162*)&q[i * 4] = p;
    p.x = __float2bfloat16(ternf(v.z)); p.y = __float2bfloat16(ternf(v.w));
    *(__nv_bfloat162*)&q[i * 4 + 2] = p;
}

__global__ __launch_bounds__(256)
void splitx_kernel(const float* __restrict__ x){
    size_t i = (size_t)blockIdx.x * 256 + threadIdx.x;
    float4 v = ((const float4*)x)[i];
    __nv_bfloat16 h0 = __float2bfloat16(v.x), h1 = __float2bfloat16(v.y);
    __nv_bfloat16 h2 = __float2bfloat16(v.z), h3 = __float2bfloat16(v.w);
    __nv_bfloat162 p;
    p.x = h0; p.y = h1; *(__nv_bfloat162*)&g_xhi[i * 4]     = p;
    p.x = h2; p.y = h3; *(__nv_bfloat162*)&g_xhi[i * 4 + 2] = p;
    p.x = __float2bfloat16(v.x - __bfloat162float(h0));
    p.y = __float2bfloat16(v.y - __bfloat162float(h1));
    *(__nv_bfloat162*)&g_xlo[i * 4] = p;
    p.x = __float2bfloat16(v.z - __bfloat162float(h2));
    p.y = __float2bfloat16(v.w - __bfloat162float(h3));
    *(__nv_bfloat162*)&g_xlo[i * 4 + 2] = p;
}

// ---------------- launch -----------------------------------------------------
extern "C" void kernel_launch(void* const* d_in, const int* in_sizes, int n_in,
                              void* d_out, int out_size){
    const float* x    = (const float*)d_in[0];
    const float* w1   = (const float*)d_in[1];
    const float* b1   = (const float*)d_in[2];
    const float* s1   = (const float*)d_in[3];
    const float* w2   = (const float*)d_in[4];
    const float* b2   = (const float*)d_in[5];
    const float* s2   = (const float*)d_in[6];
    const float* ln1g = (const float*)d_in[7];
    const float* ln1b = (const float*)d_in[8];
    const float* outg = (const float*)d_in[9];
    const float* outb = (const float*)d_in[10];
    float* out = (float*)d_out;

    (void)cudaFuncSetAttribute(gemm_kernel<1, D_H, D_IN>,
                               cudaFuncAttributeMaxDynamicSharedMemorySize, GEMM_SMEM);
    (void)cudaFuncSetAttribute(gemm_kernel<2, D_OUT, D_H>,
                               cudaFuncAttributeMaxDynamicSharedMemorySize, GEMM_SMEM);

    quant_kernel<<<16384, 256>>>(w1, 1);
    quant_kernel<<<16384, 256>>>(w2, 2);
    splitx_kernel<<<16384, 256>>>(x);

    gemm_kernel<1, D_H, D_IN>
        <<<(N_ROWS / BM) * (D_H / BN), 256, GEMM_SMEM>>>(b1, s1);
    ln1_kernel<<<N_ROWS, 256>>>(ln1g, ln1b);
    gemm_kernel<2, D_OUT, D_H>
        <<<(N_ROWS / BM) * (D_OUT / BN), 256, GEMM_SMEM>>>(b2, s2);
    ln2_kernel<<<N_ROWS, 256>>>(outg, outb, out);
}

// round 16
// speedup vs baseline: 1.0227x; 1.0011x over previous
#include <cuda_runtime.h>
#include <cuda_bf16.h>
#include <cstdint>
#include <cstddef>

#define DI __device__ __forceinline__

static constexpr int N_ROWS = 8192;   // batch rows
static constexpr int D_IN   = 2048;
static constexpr int D_H    = 8192;
static constexpr int D_OUT  = 2048;

// ---------------- scratch (device globals; no allocation allowed) ----------
__device__ __align__(16) __nv_bfloat16 g_w1q[(size_t)D_H  * D_IN ];
__device__ __align__(16) __nv_bfloat16 g_w2q[(size_t)D_OUT * D_H ];
__device__ __align__(16) __nv_bfloat16 g_xhi[(size_t)N_ROWS * D_IN];
__device__ __align__(16) __nv_bfloat16 g_xlo[(size_t)N_ROWS * D_IN];
__device__ __align__(16) float         g_h  [(size_t)N_ROWS * D_H ];
__device__ __align__(16) __nv_bfloat16 g_hhi[(size_t)N_ROWS * D_H ];
__device__ __align__(16) __nv_bfloat16 g_hlo[(size_t)N_ROWS * D_H ];
__device__ __align__(16) float         g_o  [(size_t)N_ROWS * D_OUT];

// ---------------- PTX helpers ----------------------------------------------
DI uint32_t smem_u32(const void* p){ return (uint32_t)__cvta_generic_to_shared(p); }

DI void cp_async16(uint32_t dst, const void* src){
    asm volatile("cp.async.cg.shared.global [%0], [%1], 16;\n" :: "r"(dst), "l"(src));
}
DI void cp_commit(){ asm volatile("cp.async.commit_group;\n"); }
template<int N> DI void cp_wait(){ asm volatile("cp.async.wait_group %0;\n" :: "n"(N)); }

DI void ldsm4(uint32_t& r0, uint32_t& r1, uint32_t& r2, uint32_t& r3, uint32_t a){
    asm volatile("ldmatrix.sync.aligned.m8n8.x4.shared.b16 {%0,%1,%2,%3}, [%4];\n"
        : "=r"(r0), "=r"(r1), "=r"(r2), "=r"(r3) : "r"(a));
}
DI void mma16816(float* d, const uint32_t* a, uint32_t b0, uint32_t b1){
    asm volatile("mma.sync.aligned.m16n8k16.row.col.f32.bf16.bf16.f32 "
        "{%0,%1,%2,%3}, {%4,%5,%6,%7}, {%8,%9}, {%0,%1,%2,%3};\n"
        : "+f"(d[0]), "+f"(d[1]), "+f"(d[2]), "+f"(d[3])
        : "r"(a[0]), "r"(a[1]), "r"(a[2]), "r"(a[3]), "r"(b0), "r"(b1));
}

// ---------------- GEMM: C = (Ahi+Alo) @ B^T, epilogue (acc+bias)*scale ------
// CTA tile 128x256x64, 8 warps in 2x4 -> warp tile 64x64.
static constexpr int BM = 128, BN = 256, BK = 64, STAGES = 3;
static constexpr int A_BYTES     = BM * BK * 2;             // 16384
static constexpr int B_BYTES     = BN * BK * 2;             // 32768
static constexpr int STAGE_BYTES = 2 * A_BYTES + B_BYTES;   // 65536
static constexpr int SM_BIAS     = 0;                       // 256 floats
static constexpr int SM_SCALE    = 1024;                    // 256 floats
static constexpr int SM_STAGE0   = 2048;
static constexpr int GEMM_SMEM   = SM_STAGE0 + STAGES * STAGE_BYTES;  // 198656

// tile: ROWS rows x 64 bf16 (128B rows). 16B-chunk swizzle: phys_chunk = chunk^(row&7).
template<int ROWS>
DI void load_tile(char* dst, const __nv_bfloat16* __restrict__ src,
                  int ld, int row0, int k0, int tid){
    #pragma unroll
    for (int i = 0; i < ROWS / 32; i++){
        int lin = tid + i * 256;
        int r = lin >> 3;
        int c = lin & 7;
        int cs = c ^ (r & 7);
        cp_async16(smem_u32(dst + ((r << 6) + (cs << 3)) * 2),
                   src + (size_t)(row0 + r) * ld + k0 + (c << 3));
    }
}

template<int LAYER, int Ndim, int Kdim>
__global__ __launch_bounds__(256, 1)
void gemm_kernel(const float* __restrict__ bias, const float* __restrict__ scale){
    extern __shared__ char smem[];
    const __nv_bfloat16* Ahi = (LAYER == 1) ? g_xhi : g_hhi;
    const __nv_bfloat16* Alo = (LAYER == 1) ? g_xlo : g_hlo;
    const __nv_bfloat16* Bw  = (LAYER == 1) ? g_w1q : g_w2q;
    float* C = (LAYER == 1) ? g_h : g_o;

    constexpr int NBN = Ndim / BN;
    constexpr int KT  = Kdim / BK;

    // CTA swizzle: groups of 8 M-blocks share B columns in L2
    int bid = blockIdx.x;
    int grp = bid / (8 * NBN);
    int rem = bid % (8 * NBN);
    int bm  = grp * 8 + (rem & 7);
    int bn  = rem >> 3;

    int tid  = threadIdx.x;
    int lane = tid & 31;
    int wid  = tid >> 5;
    int wm   = (wid >> 2) * 64;   // 0 / 64
    int wn   = (wid & 3) * 64;    // 0 / 64 / 128 / 192

    // stage bias/scale for this CTA's 256 output cols
    ((float*)(smem + SM_BIAS ))[tid] = bias [bn * BN + tid];
    ((float*)(smem + SM_SCALE))[tid] = scale[bn * BN + tid];

    // prologue: stages 0 .. STAGES-2
    #pragma unroll
    for (int s = 0; s < STAGES - 1; ++s){
        char* st = smem + SM_STAGE0 + s * STAGE_BYTES;
        load_tile<BM>(st,               Ahi, Kdim, bm * BM, s * BK, tid);
        load_tile<BM>(st + A_BYTES,     Alo, Kdim, bm * BM, s * BK, tid);
        load_tile<BN>(st + 2 * A_BYTES, Bw,  Kdim, bn * BN, s * BK, tid);
        cp_commit();
    }

    float acc[4][8][4];
    #pragma unroll
    for (int i = 0; i < 4; i++)
        #pragma unroll
        for (int j = 0; j < 8; j++)
            #pragma unroll
            for (int k = 0; k < 4; k++) acc[i][j][k] = 0.f;

    int cidx = 0, pidx = STAGES - 1;
    for (int kt = 0; kt < KT; ++kt){
        cp_wait<STAGES - 2>();
        __syncthreads();

        if (kt + STAGES - 1 < KT){
            char* st = smem + SM_STAGE0 + pidx * STAGE_BYTES;
            int k0 = (kt + STAGES - 1) * BK;
            load_tile<BM>(st,               Ahi, Kdim, bm * BM, k0, tid);
            load_tile<BM>(st + A_BYTES,     Alo, Kdim, bm * BM, k0, tid);
            load_tile<BN>(st + 2 * A_BYTES, Bw,  Kdim, bn * BN, k0, tid);
        }
        cp_commit();

        char* st = smem + SM_STAGE0 + cidx * STAGE_BYTES;
        uint32_t sa = smem_u32(st);
        uint32_t sl = sa + A_BYTES;
        uint32_t sb = sa + 2 * A_BYTES;

        #pragma unroll
        for (int kk = 0; kk < 4; ++kk){
            // B fragments: 64 N-rows = 4 ldsm.x4 groups
            uint32_t bb[4][4];
            #pragma unroll
            for (int pj = 0; pj < 4; pj++){
                int r  = wn + pj * 16 + (lane & 15);
                int ch = ((kk << 1) + (lane >> 4)) ^ (r & 7);
                uint32_t off = (uint32_t)((r << 6) + (ch << 3)) * 2;
                ldsm4(bb[pj][0], bb[pj][1], bb[pj][2], bb[pj][3], sb + off);
            }
            // A hi then A lo, reusing one fragment array
            #pragma unroll
            for (int p = 0; p < 2; p++){
                uint32_t base = p ? sl : sa;
                uint32_t aa[4][4];
                #pragma unroll
                for (int mi = 0; mi < 4; mi++){
                    int r  = wm + mi * 16 + (lane & 15);
                    int ch = ((kk << 1) + (lane >> 4)) ^ (r & 7);
                    uint32_t off = (uint32_t)((r << 6) + (ch << 3)) * 2;
                    ldsm4(aa[mi][0], aa[mi][1], aa[mi][2], aa[mi][3], base + off);
                }
                #pragma unroll
                for (int mi = 0; mi < 4; mi++)
                    #pragma unroll
                    for (int ni = 0; ni < 8; ni++)
                        mma16816(acc[mi][ni], aa[mi],
                                 bb[ni >> 1][ni & 1], bb[ni >> 1][(ni & 1) + 2]);
            }
        }
        if (++cidx == STAGES) cidx = 0;
        if (++pidx == STAGES) pidx = 0;
    }

    // epilogue: (acc + bias[n]) * scale[n], fp32 out
    const float* sbv = (const float*)(smem + SM_BIAS);
    const float* ssv = (const float*)(smem + SM_SCALE);
    #pragma unroll
    for (int mi = 0; mi < 4; mi++){
        #pragma unroll
        for (int hh = 0; hh < 2; ++hh){
            int r = bm * BM + wm + mi * 16 + hh * 8 + (lane >> 2);
            float* Crow = C + (size_t)r * Ndim + bn * BN;
            #pragma unroll
            for (int ni = 0; ni < 8; ni++){
                int c = wn + ni * 8 + ((lane & 3) << 1);
                float2 o;
                o.x = (acc[mi][ni][hh * 2 + 0] + sbv[c + 0]) * ssv[c + 0];
                o.y = (acc[mi][ni][hh * 2 + 1] + sbv[c + 1]) * ssv[c + 1];
                *(float2*)&Crow[c] = o;
            }
        }
    }
}

// ---------------- reductions / LayerNorm ------------------------------------
DI float block_reduce(float v, volatile float* buf){
    #pragma unroll
    for (int o = 16; o; o >>= 1) v += __shfl_xor_sync(0xffffffffu, v, o);
    int w = threadIdx.x >> 5, l = threadIdx.x & 31;
    if (l == 0) buf[w] = v;
    __syncthreads();
    if (threadIdx.x < 32){
        v = (l < 8) ? buf[l] : 0.f;
        #pragma unroll
        for (int o = 4; o; o >>= 1) v += __shfl_xor_sync(0xffffffffu, v, o);
        if (l == 0) buf[0] = v;
    }
    __syncthreads();
    return buf[0];
}

// LN(+relu) over D_H, then split to bf16 hi/lo for GEMM2
__global__ __launch_bounds__(256)
void ln1_kernel(const float* __restrict__ gam, const float* __restrict__ bet){
    __shared__ float red[40];
    size_t row = blockIdx.x;
    const float4* h4 = (const float4*)(g_h + row * D_H);
    float4 v[8];
    float sum = 0.f, sq = 0.f;
    #pragma unroll
    for (int i = 0; i < 8; i++){
        v[i] = h4[threadIdx.x + i * 256];
        sum += v[i].x + v[i].y + v[i].z + v[i].w;
        sq  += v[i].x * v[i].x + v[i].y * v[i].y + v[i].z * v[i].z + v[i].w * v[i].w;
    }
    sum = block_reduce(sum, red);
    sq  = block_reduce(sq,  red + 20);
    float mu   = sum * (1.f / D_H);
    float var  = sq * (1.f / D_H) - mu * mu;
    float rstd = rsqrtf(var + 1e-5f);

    __nv_bfloat16* hhi = g_hhi + row * D_H;
    __nv_bfloat16* hlo = g_hlo + row * D_H;
    #pragma unroll
    for (int i = 0; i < 8; i++){
        int c = (threadIdx.x + i * 256) * 4;
        float4 gg = *(const float4*)&gam[c];
        float4 bb = *(const float4*)&bet[c];
        float y0 = fmaxf((v[i].x - mu) * rstd * gg.x + bb.x, 0.f);
        float y1 = fmaxf((v[i].y - mu) * rstd * gg.y + bb.y, 0.f);
        float y2 = fmaxf((v[i].z - mu) * rstd * gg.z + bb.z, 0.f);
        float y3 = fmaxf((v[i].w - mu) * rstd * gg.w + bb.w, 0.f);
        __nv_bfloat16 h0 = __float2bfloat16(y0), h1 = __float2bfloat16(y1);
        __nv_bfloat16 h2 = __float2bfloat16(y2), h3 = __float2bfloat16(y3);
        __nv_bfloat162 p;
        p.x = h0; p.y = h1; *(__nv_bfloat162*)&hhi[c]     = p;
        p.x = h2; p.y = h3; *(__nv_bfloat162*)&hhi[c + 2] = p;
        p.x = __float2bfloat16(y0 - __bfloat162float(h0));
        p.y = __float2bfloat16(y1 - __bfloat162float(h1));
        *(__nv_bfloat162*)&hlo[c] = p;
        p.x = __float2bfloat16(y2 - __bfloat162float(h2));
        p.y = __float2bfloat16(y3 - __bfloat162float(h3));
        *(__nv_bfloat162*)&hlo[c + 2] = p;
    }
}

// final LN over D_OUT -> d_out (fp32)
__global__ __launch_bounds__(256)
void ln2_kernel(const float* __restrict__ gam, const float* __restrict__ bet,
                float* __restrict__ out){
    __shared__ float red[40];
    size_t row = blockIdx.x;
    const float4* o4 = (const float4*)(g_o + row * D_OUT);
    float4 v[2];
    float sum = 0.f, sq = 0.f;
    #pragma unroll
    for (int i = 0; i < 2; i++){
        v[i] = o4[threadIdx.x + i * 256];
        sum += v[i].x + v[i].y + v[i].z + v[i].w;
        sq  += v[i].x * v[i].x + v[i].y * v[i].y + v[i].z * v[i].z + v[i].w * v[i].w;
    }
    sum = block_reduce(sum, red);
    sq  = block_reduce(sq,  red + 20);
    float mu   = sum * (1.f / D_OUT);
    float var  = sq * (1.f / D_OUT) - mu * mu;
    float rstd = rsqrtf(var + 1e-5f);

    float4* out4 = (float4*)(out + row * D_OUT);
    #pragma unroll
    for (int i = 0; i < 2; i++){
        int idx = threadIdx.x + i * 256;
        int c = idx * 4;
        float4 gg = *(const float4*)&gam[c];
        float4 bb = *(const float4*)&bet[c];
        float4 r;
        r.x = (v[i].x - mu) * rstd * gg.x + bb.x;
        r.y = (v[i].y - mu) * rstd * gg.y + bb.y;
        r.z = (v[i].z - mu) * rstd * gg.z + bb.z;
        r.w = (v[i].w - mu) * rstd * gg.w + bb.w;
        out4[idx] = r;
    }
}

// ---------------- prep: ternary-quantize weights, split activations ---------
DI float ternf(float x){ return (fabsf(x) < 0.1f) ? 0.f : (x > 0.f ? 1.f : -1.f); }

__global__ __launch_bounds__(256)
void quant_kernel(const float* __restrict__ w, int which){
    __nv_bfloat16* q = (which == 1) ? g_w1q : g_w2q;
    size_t i = (size_t)blockIdx.x * 256 + threadIdx.x;
    float4 v = ((const float4*)w)[i];
    __nv_bfloat162 p;
    p.x = __float2bfloat16(ternf(v.x)); p.y = __float2bfloat16(ternf(v.y));
    *(__nv_bfloat162*)&q[i * 4] = p;
    p.x = __float2bfloat16(ternf(v.z)); p.y = __float2bfloat16(ternf(v.w));
    *(__nv_bfloat162*)&q[i * 4 + 2] = p;
}

__global__ __launch_bounds__(256)
void splitx_kernel(const float* __restrict__ x){
    size_t i = (size_t)blockIdx.x * 256 + threadIdx.x;
    float4 v = ((const float4*)x)[i];
    __nv_bfloat16 h0 = __float2bfloat16(v.x), h1 = __float2bfloat16(v.y);
    __nv_bfloat16 h2 = __float2bfloat16(v.z), h3 = __float2bfloat16(v.w);
    __nv_bfloat162 p;
    p.x = h0; p.y = h1; *(__nv_bfloat162*)&g_xhi[i * 4]     = p;
    p.x = h2; p.y = h3; *(__nv_bfloat162*)&g_xhi[i * 4 + 2] = p;
    p.x = __float2bfloat16(v.x - __bfloat162float(h0));
    p.y = __float2bfloat16(v.y - __bfloat162float(h1));
    *(__nv_bfloat162*)&g_xlo[i * 4] = p;
    p.x = __float2bfloat16(v.z - __bfloat162float(h2));
    p.y = __float2bfloat16(v.w - __bfloat162float(h3));
    *(__nv_bfloat162*)&g_xlo[i * 4 + 2] = p;
}

// ---------------- launch -----------------------------------------------------
extern "C" void kernel_launch(void* const* d_in, const int* in_sizes, int n_in,
                              void* d_out, int out_size){
    const float* x    = (const float*)d_in[0];
    const float* w1   = (const float*)d_in[1];
    const float* b1   = (const float*)d_in[2];
    const float* s1   = (const float*)d_in[3];
    const float* w2   = (const float*)d_in[4];
    const float* b2   = (const float*)d_in[5];
    const float* s2   = (const float*)d_in[6];
    const float* ln1g = (const float*)d_in[7];
    const float* ln1b = (const float*)d_in[8];
    const float* outg = (const float*)d_in[9];
    const float* outb = (const float*)d_in[10];
    float* out = (float*)d_out;

    (void)cudaFuncSetAttribute(gemm_kernel<1, D_H, D_IN>,
                               cudaFuncAttributeMaxDynamicSharedMemorySize, GEMM_SMEM);
    (void)cudaFuncSetAttribute(gemm_kernel<2, D_OUT, D_H>,
                               cudaFuncAttributeMaxDynamicSharedMemorySize, GEMM_SMEM);

    quant_kernel<<<16384, 256>>>(w1, 1);
    quant_kernel<<<16384, 256>>>(w2, 2);
    splitx_kernel<<<16384, 256>>>(x);

    gemm_kernel<1, D_H, D_IN>
        <<<(N_ROWS / BM) * (D_H / BN), 256, GEMM_SMEM>>>(b1, s1);
    ln1_kernel<<<N_ROWS, 256>>>(ln1g, ln1b);
    gemm_kernel<2, D_OUT, D_H>
        <<<(N_ROWS / BM) * (D_OUT / BN), 256, GEMM_SMEM>>>(b2, s2);
    ln2_kernel<<<N_ROWS, 256>>>(outg, outb, out);
}

// round 17
// speedup vs baseline: 1.0233x; 1.0006x over previous
#include <cuda_runtime.h>
#include <cuda_bf16.h>
#include <cstdint>
#include <cstddef>

#define DI __device__ __forceinline__

static constexpr int N_ROWS = 8192;   // batch rows
static constexpr int D_IN   = 2048;
static constexpr int D_H    = 8192;
static constexpr int D_OUT  = 2048;

// ---------------- scratch (device globals; no allocation allowed) ----------
__device__ __align__(16) __nv_bfloat16 g_w1q[(size_t)D_H  * D_IN ];
__device__ __align__(16) __nv_bfloat16 g_w2q[(size_t)D_OUT * D_H ];
__device__ __align__(16) __nv_bfloat16 g_xhi[(size_t)N_ROWS * D_IN];
__device__ __align__(16) __nv_bfloat16 g_xlo[(size_t)N_ROWS * D_IN];
__device__ __align__(16) float         g_h  [(size_t)N_ROWS * D_H ];
__device__ __align__(16) __nv_bfloat16 g_hhi[(size_t)N_ROWS * D_H ];
__device__ __align__(16) __nv_bfloat16 g_hlo[(size_t)N_ROWS * D_H ];
__device__ __align__(16) float         g_o  [(size_t)N_ROWS * D_OUT];

// ---------------- PTX helpers ----------------------------------------------
DI uint32_t smem_u32(const void* p){ return (uint32_t)__cvta_generic_to_shared(p); }

DI void cp_async16(uint32_t dst, const void* src){
    asm volatile("cp.async.cg.shared.global [%0], [%1], 16;\n" :: "r"(dst), "l"(src));
}
DI void cp_commit(){ asm volatile("cp.async.commit_group;\n"); }
template<int N> DI void cp_wait(){ asm volatile("cp.async.wait_group %0;\n" :: "n"(N)); }

DI void ldsm4(uint32_t& r0, uint32_t& r1, uint32_t& r2, uint32_t& r3, uint32_t a){
    asm volatile("ldmatrix.sync.aligned.m8n8.x4.shared.b16 {%0,%1,%2,%3}, [%4];\n"
        : "=r"(r0), "=r"(r1), "=r"(r2), "=r"(r3) : "r"(a));
}
DI void mma16816(float* d, const uint32_t* a, uint32_t b0, uint32_t b1){
    asm volatile("mma.sync.aligned.m16n8k16.row.col.f32.bf16.bf16.f32 "
        "{%0,%1,%2,%3}, {%4,%5,%6,%7}, {%8,%9}, {%0,%1,%2,%3};\n"
        : "+f"(d[0]), "+f"(d[1]), "+f"(d[2]), "+f"(d[3])
        : "r"(a[0]), "r"(a[1]), "r"(a[2]), "r"(a[3]), "r"(b0), "r"(b1));
}

// ---------------- GEMM: C = (Ahi+Alo) @ B^T, epilogue (acc+bias)*scale ------
// CTA tile 128x256x64, 8 warps in 2x4 -> warp tile 64x64.
static constexpr int BM = 128, BN = 256, BK = 64, STAGES = 3;
static constexpr int A_BYTES     = BM * BK * 2;             // 16384
static constexpr int B_BYTES     = BN * BK * 2;             // 32768
static constexpr int STAGE_BYTES = 2 * A_BYTES + B_BYTES;   // 65536
static constexpr int SM_BIAS     = 0;                       // 256 floats
static constexpr int SM_SCALE    = 1024;                    // 256 floats
static constexpr int SM_STAGE0   = 2048;
static constexpr int GEMM_SMEM   = SM_STAGE0 + STAGES * STAGE_BYTES;  // 198656

// tile: ROWS rows x 64 bf16 (128B rows). 16B-chunk swizzle: phys_chunk = chunk^(row&7).
template<int ROWS>
DI void load_tile(char* dst, const __nv_bfloat16* __restrict__ src,
                  int ld, int row0, int k0, int tid){
    #pragma unroll
    for (int i = 0; i < ROWS / 32; i++){
        int lin = tid + i * 256;
        int r = lin >> 3;
        int c = lin & 7;
        int cs = c ^ (r & 7);
        cp_async16(smem_u32(dst + ((r << 6) + (cs << 3)) * 2),
                   src + (size_t)(row0 + r) * ld + k0 + (c << 3));
    }
}

template<int LAYER, int Ndim, int Kdim>
__global__ __launch_bounds__(256, 1)
void gemm_kernel(const float* __restrict__ bias, const float* __restrict__ scale){
    extern __shared__ char smem[];
    const __nv_bfloat16* Ahi = (LAYER == 1) ? g_xhi : g_hhi;
    const __nv_bfloat16* Alo = (LAYER == 1) ? g_xlo : g_hlo;
    const __nv_bfloat16* Bw  = (LAYER == 1) ? g_w1q : g_w2q;
    float* C = (LAYER == 1) ? g_h : g_o;

    constexpr int NBN = Ndim / BN;
    constexpr int KT  = Kdim / BK;

    // CTA swizzle: groups of 8 M-blocks share B columns in L2
    int bid = blockIdx.x;
    int grp = bid / (8 * NBN);
    int rem = bid % (8 * NBN);
    int bm  = grp * 8 + (rem & 7);
    int bn  = rem >> 3;

    int tid  = threadIdx.x;
    int lane = tid & 31;
    int wid  = tid >> 5;
    int wm   = (wid >> 2) * 64;   // 0 / 64
    int wn   = (wid & 3) * 64;    // 0 / 64 / 128 / 192

    // stage bias/scale for this CTA's 256 output cols
    ((float*)(smem + SM_BIAS ))[tid] = bias [bn * BN + tid];
    ((float*)(smem + SM_SCALE))[tid] = scale[bn * BN + tid];

    // prologue: stages 0 .. STAGES-2
    #pragma unroll
    for (int s = 0; s < STAGES - 1; ++s){
        char* st = smem + SM_STAGE0 + s * STAGE_BYTES;
        load_tile<BM>(st,               Ahi, Kdim, bm * BM, s * BK, tid);
        load_tile<BM>(st + A_BYTES,     Alo, Kdim, bm * BM, s * BK, tid);
        load_tile<BN>(st + 2 * A_BYTES, Bw,  Kdim, bn * BN, s * BK, tid);
        cp_commit();
    }

    float acc[4][8][4];
    #pragma unroll
    for (int i = 0; i < 4; i++)
        #pragma unroll
        for (int j = 0; j < 8; j++)
            #pragma unroll
            for (int k = 0; k < 4; k++) acc[i][j][k] = 0.f;

    int cidx = 0, pidx = STAGES - 1;
    for (int kt = 0; kt < KT; ++kt){
        cp_wait<STAGES - 2>();
        __syncthreads();

        if (kt + STAGES - 1 < KT){
            char* st = smem + SM_STAGE0 + pidx * STAGE_BYTES;
            int k0 = (kt + STAGES - 1) * BK;
            load_tile<BM>(st,               Ahi, Kdim, bm * BM, k0, tid);
            load_tile<BM>(st + A_BYTES,     Alo, Kdim, bm * BM, k0, tid);
            load_tile<BN>(st + 2 * A_BYTES, Bw,  Kdim, bn * BN, k0, tid);
        }
        cp_commit();

        char* st = smem + SM_STAGE0 + cidx * STAGE_BYTES;
        uint32_t sa = smem_u32(st);
        uint32_t sl = sa + A_BYTES;
        uint32_t sb = sa + 2 * A_BYTES;

        #pragma unroll
        for (int kk = 0; kk < 4; ++kk){
            // B fragments: 64 N-rows = 4 ldsm.x4 groups
            uint32_t bb[4][4];
            #pragma unroll
            for (int pj = 0; pj < 4; pj++){
                int r  = wn + pj * 16 + (lane & 15);
                int ch = ((kk << 1) + (lane >> 4)) ^ (r & 7);
                uint32_t off = (uint32_t)((r << 6) + (ch << 3)) * 2;
                ldsm4(bb[pj][0], bb[pj][1], bb[pj][2], bb[pj][3], sb + off);
            }
            // A hi then A lo, reusing one fragment array
            #pragma unroll
            for (int p = 0; p < 2; p++){
                uint32_t base = p ? sl : sa;
                uint32_t aa[4][4];
                #pragma unroll
                for (int mi = 0; mi < 4; mi++){
                    int r  = wm + mi * 16 + (lane & 15);
                    int ch = ((kk << 1) + (lane >> 4)) ^ (r & 7);
                    uint32_t off = (uint32_t)((r << 6) + (ch << 3)) * 2;
                    ldsm4(aa[mi][0], aa[mi][1], aa[mi][2], aa[mi][3], base + off);
                }
                #pragma unroll
                for (int mi = 0; mi < 4; mi++)
                    #pragma unroll
                    for (int ni = 0; ni < 8; ni++)
                        mma16816(acc[mi][ni], aa[mi],
                                 bb[ni >> 1][ni & 1], bb[ni >> 1][(ni & 1) + 2]);
            }
        }
        if (++cidx == STAGES) cidx = 0;
        if (++pidx == STAGES) pidx = 0;
    }

    // epilogue: (acc + bias[n]) * scale[n], fp32 out
    const float* sbv = (const float*)(smem + SM_BIAS);
    const float* ssv = (const float*)(smem + SM_SCALE);
    #pragma unroll
    for (int mi = 0; mi < 4; mi++){
        #pragma unroll
        for (int hh = 0; hh < 2; ++hh){
            int r = bm * BM + wm + mi * 16 + hh * 8 + (lane >> 2);
            float* Crow = C + (size_t)r * Ndim + bn * BN;
            #pragma unroll
            for (int ni = 0; ni < 8; ni++){
                int c = wn + ni * 8 + ((lane & 3) << 1);
                float2 o;
                o.x = (acc[mi][ni][hh * 2 + 0] + sbv[c + 0]) * ssv[c + 0];
                o.y = (acc[mi][ni][hh * 2 + 1] + sbv[c + 1]) * ssv[c + 1];
                *(float2*)&Crow[c] = o;
            }
        }
    }
}

// ---------------- reductions / LayerNorm ------------------------------------
DI float block_reduce(float v, volatile float* buf){
    #pragma unroll
    for (int o = 16; o; o >>= 1) v += __shfl_xor_sync(0xffffffffu, v, o);
    int w = threadIdx.x >> 5, l = threadIdx.x & 31;
    if (l == 0) buf[w] = v;
    __syncthreads();
    if (threadIdx.x < 32){
        v = (l < 8) ? buf[l] : 0.f;
        #pragma unroll
        for (int o = 4; o; o >>= 1) v += __shfl_xor_sync(0xffffffffu, v, o);
        if (l == 0) buf[0] = v;
    }
    __syncthreads();
    return buf[0];
}

// LN(+relu) over D_H, then split to bf16 hi/lo for GEMM2
__global__ __launch_bounds__(256)
void ln1_kernel(const float* __restrict__ gam, const float* __restrict__ bet){
    __shared__ float red[40];
    size_t row = blockIdx.x;
    const float4* h4 = (const float4*)(g_h + row * D_H);
    float4 v[8];
    float sum = 0.f, sq = 0.f;
    #pragma unroll
    for (int i = 0; i < 8; i++){
        v[i] = h4[threadIdx.x + i * 256];
        sum += v[i].x + v[i].y + v[i].z + v[i].w;
        sq  += v[i].x * v[i].x + v[i].y * v[i].y + v[i].z * v[i].z + v[i].w * v[i].w;
    }
    sum = block_reduce(sum, red);
    sq  = block_reduce(sq,  red + 20);
    float mu   = sum * (1.f / D_H);
    float var  = sq * (1.f / D_H) - mu * mu;
    float rstd = rsqrtf(var + 1e-5f);

    __nv_bfloat16* hhi = g_hhi + row * D_H;
    __nv_bfloat16* hlo = g_hlo + row * D_H;
    #pragma unroll
    for (int i = 0; i < 8; i++){
        int c = (threadIdx.x + i * 256) * 4;
        float4 gg = *(const float4*)&gam[c];
        float4 bb = *(const float4*)&bet[c];
        float y0 = fmaxf((v[i].x - mu) * rstd * gg.x + bb.x, 0.f);
        float y1 = fmaxf((v[i].y - mu) * rstd * gg.y + bb.y, 0.f);
        float y2 = fmaxf((v[i].z - mu) * rstd * gg.z + bb.z, 0.f);
        float y3 = fmaxf((v[i].w - mu) * rstd * gg.w + bb.w, 0.f);
        __nv_bfloat16 h0 = __float2bfloat16(y0), h1 = __float2bfloat16(y1);
        __nv_bfloat16 h2 = __float2bfloat16(y2), h3 = __float2bfloat16(y3);
        __nv_bfloat162 p;
        p.x = h0; p.y = h1; *(__nv_bfloat162*)&hhi[c]     = p;
        p.x = h2; p.y = h3; *(__nv_bfloat162*)&hhi[c + 2] = p;
        p.x = __float2bfloat16(y0 - __bfloat162float(h0));
        p.y = __float2bfloat16(y1 - __bfloat162float(h1));
        *(__nv_bfloat162*)&hlo[c] = p;
        p.x = __float2bfloat16(y2 - __bfloat162float(h2));
        p.y = __float2bfloat16(y3 - __bfloat162float(h3));
        *(__nv_bfloat162*)&hlo[c + 2] = p;
    }
}

// final LN over D_OUT -> d_out (fp32)
__global__ __launch_bounds__(256)
void ln2_kernel(const float* __restrict__ gam, const float* __restrict__ bet,
                float* __restrict__ out){
    __shared__ float red[40];
    size_t row = blockIdx.x;
    const float4* o4 = (const float4*)(g_o + row * D_OUT);
    float4 v[2];
    float sum = 0.f, sq = 0.f;
    #pragma unroll
    for (int i = 0; i < 2; i++){
        v[i] = o4[threadIdx.x + i * 256];
        sum += v[i].x + v[i].y + v[i].z + v[i].w;
        sq  += v[i].x * v[i].x + v[i].y * v[i].y + v[i].z * v[i].z + v[i].w * v[i].w;
    }
    sum = block_reduce(sum, red);
    sq  = block_reduce(sq,  red + 20);
    float mu   = sum * (1.f / D_OUT);
    float var  = sq * (1.f / D_OUT) - mu * mu;
    float rstd = rsqrtf(var + 1e-5f);

    float4* out4 = (float4*)(out + row * D_OUT);
    #pragma unroll
    for (int i = 0; i < 2; i++){
        int idx = threadIdx.x + i * 256;
        int c = idx * 4;
        float4 gg = *(const float4*)&gam[c];
        float4 bb = *(const float4*)&bet[c];
        float4 r;
        r.x = (v[i].x - mu) * rstd * gg.x + bb.x;
        r.y = (v[i].y - mu) * rstd * gg.y + bb.y;
        r.z = (v[i].z - mu) * rstd * gg.z + bb.z;
        r.w = (v[i].w - mu) * rstd * gg.w + bb.w;
        out4[idx] = r;
    }
}

// ---------------- prep: ternary-quantize weights, split activations ---------
DI float ternf(float x){ return (fabsf(x) < 0.1f) ? 0.f : (x > 0.f ? 1.f : -1.f); }

__global__ __launch_bounds__(256)
void quant_kernel(const float* __restrict__ w, int which){
    __nv_bfloat16* q = (which == 1) ? g_w1q : g_w2q;
    size_t i = (size_t)blockIdx.x * 256 + threadIdx.x;
    float4 v = ((const float4*)w)[i];
    __nv_bfloat162 p;
    p.x = __float2bfloat16(ternf(v.x)); p.y = __float2bfloat16(ternf(v.y));
    *(__nv_bfloat162*)&q[i * 4] = p;
    p.x = __float2bfloat16(ternf(v.z)); p.y = __float2bfloat16(ternf(v.w));
    *(__nv_bfloat162*)&q[i * 4 + 2] = p;
}

__global__ __launch_bounds__(256)
void splitx_kernel(const float* __restrict__ x){
    size_t i = (size_t)blockIdx.x * 256 + threadIdx.x;
    float4 v = ((const float4*)x)[i];
    __nv_bfloat16 h0 = __float2bfloat16(v.x), h1 = __float2bfloat16(v.y);
    __nv_bfloat16 h2 = __float2bfloat16(v.z), h3 = __float2bfloat16(v.w);
    __nv_bfloat162 p;
    p.x = h0; p.y = h1; *(__nv_bfloat162*)&g_xhi[i * 4]     = p;
    p.x = h2; p.y = h3; *(__nv_bfloat162*)&g_xhi[i * 4 + 2] = p;
    p.x = __float2bfloat16(v.x - __bfloat162float(h0));
    p.y = __float2bfloat16(v.y - __bfloat162float(h1));
    *(__nv_bfloat162*)&g_xlo[i * 4] = p;
    p.x = __float2bfloat16(v.z - __bfloat162float(h2));
    p.y = __float2bfloat16(v.w - __bfloat162float(h3));
    *(__nv_bfloat162*)&g_xlo[i * 4 + 2] = p;
}

// ---------------- launch -----------------------------------------------------
extern "C" void kernel_launch(void* const* d_in, const int* in_sizes, int n_in,
                              void* d_out, int out_size){
    const float* x    = (const float*)d_in[0];
    const float* w1   = (const float*)d_in[1];
    const float* b1   = (const float*)d_in[2];
    const float* s1   = (const float*)d_in[3];
    const float* w2   = (const float*)d_in[4];
    const float* b2   = (const float*)d_in[5];
    const float* s2   = (const float*)d_in[6];
    const float* ln1g = (const float*)d_in[7];
    const float* ln1b = (const float*)d_in[8];
    const float* outg = (const float*)d_in[9];
    const float* outb = (const float*)d_in[10];
    float* out = (float*)d_out;

    (void)cudaFuncSetAttribute(gemm_kernel<1, D_H, D_IN>,
                               cudaFuncAttributeMaxDynamicSharedMemorySize, GEMM_SMEM);
    (void)cudaFuncSetAttribute(gemm_kernel<2, D_OUT, D_H>,
                               cudaFuncAttributeMaxDynamicSharedMemorySize, GEMM_SMEM);

    quant_kernel<<<16384, 256>>>(w1, 1);
    quant_kernel<<<16384, 256>>>(w2, 2);
    splitx_kernel<<<16384, 256>>>(x);

    gemm_kernel<1, D_H, D_IN>
        <<<(N_ROWS / BM) * (D_H / BN), 256, GEMM_SMEM>>>(b1, s1);
    ln1_kernel<<<N_ROWS, 256>>>(ln1g, ln1b);
    gemm_kernel<2, D_OUT, D_H>
        <<<(N_ROWS / BM) * (D_OUT / BN), 256, GEMM_SMEM>>>(b2, s2);
    ln2_kernel<<<N_ROWS, 256>>>(outg, outb, out);
}